// round 4
// baseline (speedup 1.0000x reference)
#include <cuda_runtime.h>
#include <math.h>

// RNN_472446402977: 4-layer tanh RNN + FC, fp32.
// B=512 S=256 D_IN=28 H=128 NC=10.
// Strategy:
//   proj_kernel: xw[t][b][:] = in_row(t,b) @ W_ih^T + (b_ih + b_hh)   (parallel GEMM, W^T stationary in smem)
//   recur_kernel: per-warp-per-batch-row recurrence h = tanh(xw_t + h @ W_hh^T), W_hh^T in smem,
//                 h in per-warp smem row, only __syncwarp per step.
//   fc_kernel: last timestep @ fc_w^T + fc_b.

#define BB 512
#define SS 256
#define DIN 28
#define HH 128
#define NC 10
#define PITCH 132   // smem row pitch in floats for W^T: multiple of 4 (float4-aligned), not mult of 32

// Scratch (allocation-free): ping-pong sequence buffers + xw buffer, each [S][B][H] fp32 = 64MB.
__device__ float g_bufA[SS * BB * HH];
__device__ float g_bufB[SS * BB * HH];
__device__ float g_bufC[SS * BB * HH];

// Accurate-enough tanh independent of --use_fast_math mapping of tanhf:
// __expf has ~2^-21 max rel error; tanh.approx (what fast-math tanhf becomes) has 2^-10.66
// which compounds over 1024 recurrent steps. This stays ~1e-6.
__device__ __forceinline__ float my_tanh(float x) {
    float ax = fabsf(x);
    float e  = __expf(-2.0f * ax);          // (0,1], no overflow
    float r  = (1.0f - e) / (1.0f + e);     // tanh(|x|)
    return copysignf(r, x);
}

// ---------------------------------------------------------------------------
// Input projection: out[row][i] = sum_j in_row[j] * W[i][j] + b1[i] + b2[i]
// row = t*B + b. If SWAPPED, input row lives at (b*S + t)*K (layer-0 x is [B][S][D]);
// otherwise at row*K (seq buffers are [t][b][h]).
// Block: 256 threads, 64 output rows, processed in 8-row staged chunks.
// Thread (g = tid&31, rr = tid>>5): computes out[rr-th row of chunk][4g..4g+3].
// Inner loop: 1 LDS.128 (W^T) + 1 LDS.32 broadcast (x) per 4 FFMA -> FFMA-pipe bound.
// ---------------------------------------------------------------------------
template <int K, bool SWAPPED>
__global__ void proj_kernel(const float* __restrict__ in, const float* __restrict__ W,
                            const float* __restrict__ b1, const float* __restrict__ b2,
                            float* __restrict__ out) {
    extern __shared__ float sm[];
    float* Wt = sm;                // [K][PITCH] -> Wt[j*PITCH + i] = W[i*K + j]
    float* xs = sm + K * PITCH;    // [8][K]
    __shared__ float bs[HH];

    const int tid = threadIdx.x;

    // Load W transposed into smem (coalesced global read; one-time STS conflicts are fine).
    for (int idx = tid; idx < HH * K; idx += 256) {
        int i = idx / K;
        int j = idx - i * K;
        Wt[j * PITCH + i] = W[idx];
    }
    if (tid < HH) bs[tid] = b1[tid] + b2[tid];
    __syncthreads();

    const int g  = tid & 31;
    const int rr = tid >> 5;
    const int row0 = blockIdx.x * 64;

    for (int c = 0; c < 8; c++) {
        // Stage 8 input rows into smem.
        for (int idx = tid; idx < 8 * K; idx += 256) {
            int r = idx / K;
            int j = idx - r * K;
            int row = row0 + c * 8 + r;
            int t = row >> 9;          // B = 512
            int b = row & 511;
            int src = SWAPPED ? (b * SS + t) * K + j : row * K + j;
            xs[r * K + j] = in[src];
        }
        __syncthreads();

        float4 acc = *reinterpret_cast<const float4*>(&bs[4 * g]);
        const float* xrow = &xs[rr * K];
#pragma unroll
        for (int j = 0; j < K; j++) {
            float hj = xrow[j];
            float4 w = *reinterpret_cast<const float4*>(&Wt[j * PITCH + 4 * g]);
            acc.x = fmaf(hj, w.x, acc.x);
            acc.y = fmaf(hj, w.y, acc.y);
            acc.z = fmaf(hj, w.z, acc.z);
            acc.w = fmaf(hj, w.w, acc.w);
        }
        int row = row0 + c * 8 + rr;
        *reinterpret_cast<float4*>(&out[row * HH + 4 * g]) = acc;
        __syncthreads();
    }
}

// ---------------------------------------------------------------------------
// Recurrence: h_t = tanh(xw[t][b][:] + h_{t-1} @ W_hh^T), writes seq[t][b][:] = h_t.
// Grid 128 x 128 threads. Warp bl owns batch row b = blockIdx.x*4 + bl:
//   * W_hh^T in smem, shared by the 4 warps (one __syncthreads after load, then none).
//   * h double-buffered in per-warp smem rows -> only __syncwarp per step.
//   * xw_{t+1} prefetched from global during step t's compute.
// Per step per warp: 512 FFMA (4 accumulators) -> bound by FFMA issue (rt_SMSP=2).
// ---------------------------------------------------------------------------
__global__ void recur_kernel(const float* __restrict__ xw, const float* __restrict__ Whh,
                             float* __restrict__ seq) {
    extern __shared__ float sm[];
    float* Wt = sm;                  // [H][PITCH]
    float* h2 = sm + HH * PITCH;     // [2][4][H]

    const int tid = threadIdx.x;
    for (int idx = tid; idx < HH * HH; idx += 128) {
        int i = idx >> 7;
        int j = idx & 127;
        Wt[j * PITCH + i] = Whh[idx];
    }
    const int g  = tid & 31;
    const int bl = tid >> 5;
    const int b  = blockIdx.x * 4 + bl;

    // h0 = 0 (buffer 0)
    *reinterpret_cast<float4*>(&h2[bl * HH + 4 * g]) = make_float4(0.f, 0.f, 0.f, 0.f);
    __syncthreads();

    const float4* xwp = reinterpret_cast<const float4*>(xw + b * HH) + g;
    float4*       sqp = reinterpret_cast<float4*>(seq + b * HH) + g;
    const int stride4 = BB * HH / 4;   // float4 stride between timesteps

    float4 xnext = __ldg(xwp);
    int cur = 0;

    for (int t = 0; t < SS; t++) {
        float4 xv = xnext;
        if (t + 1 < SS) xnext = __ldg(xwp + (t + 1) * stride4);

        float a0 = xv.x, a1 = xv.y, a2 = xv.z, a3 = xv.w;
        const float* hr = &h2[cur * 4 * HH + bl * HH];
#pragma unroll
        for (int j = 0; j < HH; j++) {
            float hj = hr[j];
            float4 w = *reinterpret_cast<const float4*>(&Wt[j * PITCH + 4 * g]);
            a0 = fmaf(hj, w.x, a0);
            a1 = fmaf(hj, w.y, a1);
            a2 = fmaf(hj, w.z, a2);
            a3 = fmaf(hj, w.w, a3);
        }
        float4 hv = make_float4(my_tanh(a0), my_tanh(a1), my_tanh(a2), my_tanh(a3));

        int nxt = cur ^ 1;
        *reinterpret_cast<float4*>(&h2[nxt * 4 * HH + bl * HH + 4 * g]) = hv;
        sqp[t * stride4] = hv;
        __syncwarp();
        cur = nxt;
    }
}

// ---------------------------------------------------------------------------
// FC: out[b][c] = last[b][:] . fc_w[c][:] + fc_b[c]
// ---------------------------------------------------------------------------
__global__ void fc_kernel(const float* __restrict__ last, const float* __restrict__ fw,
                          const float* __restrict__ fb, float* __restrict__ out) {
    int idx = blockIdx.x * blockDim.x + threadIdx.x;
    if (idx >= BB * NC) return;
    int b = idx / NC;
    int c = idx - b * NC;
    const float4* xr = reinterpret_cast<const float4*>(last + b * HH);
    const float4* wr = reinterpret_cast<const float4*>(fw + c * HH);
    float acc = fb[c];
#pragma unroll
    for (int j = 0; j < HH / 4; j++) {
        float4 x = __ldg(xr + j);
        float4 w = __ldg(wr + j);
        acc = fmaf(x.x, w.x, fmaf(x.y, w.y, fmaf(x.z, w.z, fmaf(x.w, w.w, acc))));
    }
    out[idx] = acc;
}

extern "C" void kernel_launch(void* const* d_in, const int* in_sizes, int n_in,
                              void* d_out, int out_size) {
    const float* x     = (const float*)d_in[0];
    const float* w_ih0 = (const float*)d_in[1];
    const float* w_hh0 = (const float*)d_in[2];
    const float* b_ih0 = (const float*)d_in[3];
    const float* b_hh0 = (const float*)d_in[4];
    const float* w_ih  = (const float*)d_in[5];   // [3][H][H]
    const float* w_hh  = (const float*)d_in[6];   // [3][H][H]
    const float* b_ih  = (const float*)d_in[7];   // [3][H]
    const float* b_hh  = (const float*)d_in[8];   // [3][H]
    const float* fc_w  = (const float*)d_in[9];
    const float* fc_b  = (const float*)d_in[10];
    float* out = (float*)d_out;

    float *bufA, *bufB, *bufC;
    cudaGetSymbolAddress((void**)&bufA, g_bufA);
    cudaGetSymbolAddress((void**)&bufB, g_bufB);
    cudaGetSymbolAddress((void**)&bufC, g_bufC);

    const size_t smP128 = (size_t)(128 * PITCH + 8 * 128) * 4;   // ~72.7 KB
    const size_t smP28  = (size_t)(28 * PITCH + 8 * 28) * 4;     // ~15.7 KB
    const size_t smR    = (size_t)(HH * PITCH + 2 * 4 * HH) * 4; // ~71.7 KB

    cudaFuncSetAttribute(proj_kernel<128, false>, cudaFuncAttributeMaxDynamicSharedMemorySize, (int)smP128);
    cudaFuncSetAttribute(recur_kernel,            cudaFuncAttributeMaxDynamicSharedMemorySize, (int)smR);

    const int PROJ_BLOCKS = (SS * BB) / 64;   // 2048

    // Layer 0: x -> xw (bufB) -> seq (bufA)
    proj_kernel<DIN, true><<<PROJ_BLOCKS, 256, smP28>>>(x, w_ih0, b_ih0, b_hh0, bufB);
    recur_kernel<<<128, 128, smR>>>(bufB, w_hh0, bufA);

    // Layers 1..3: ping-pong A <-> C, xw always in bufB.
    // l=0: A -> B -> C ; l=1: C -> B -> A ; l=2: A -> B -> C
    float* seqs[2] = {bufA, bufC};
    for (int l = 0; l < 3; l++) {
        float* prev = seqs[l & 1];
        float* next = seqs[(l & 1) ^ 1];
        proj_kernel<HH, false><<<PROJ_BLOCKS, 256, smP128>>>(
            prev, w_ih + l * HH * HH, b_ih + l * HH, b_hh + l * HH, bufB);
        recur_kernel<<<128, 128, smR>>>(bufB, w_hh + l * HH * HH, next);
    }

    // Final FC on last timestep of layer-3 output (bufC).
    const float* last = bufC + (size_t)(SS - 1) * BB * HH;
    fc_kernel<<<(BB * NC + 127) / 128, 128>>>(last, fc_w, fc_b, out);
}

// round 5
// speedup vs baseline: 1.6127x; 1.6127x over previous
#include <cuda_runtime.h>
#include <math.h>

// RNN_472446402977: 4-layer tanh RNN + FC, fp32.
// B=512 S=256 D_IN=28 H=128 NC=10.
// Strategy:
//   proj_kernel: xw[t][b][:] = in_row(t,b) @ W_ih^T + (b_ih + b_hh)   (parallel GEMM, W^T stationary in smem)
//   recur_kernel: per-warp-per-batch-row recurrence h = tanh(xw_t + h @ W_hh^T), W_hh^T in smem,
//                 h in per-warp smem row, only __syncwarp per step.
//   fc_kernel: last timestep @ fc_w^T + fc_b.

#define BB 512
#define SS 256
#define DIN 28
#define HH 128
#define NC 10
#define PITCH 132   // smem row pitch in floats for W^T: multiple of 4 (float4-aligned), not mult of 32

// Scratch (allocation-free): ping-pong sequence buffers + xw buffer, each [S][B][H] fp32 = 64MB.
__device__ float g_bufA[SS * BB * HH];
__device__ float g_bufB[SS * BB * HH];
__device__ float g_bufC[SS * BB * HH];

// Accurate-enough tanh independent of --use_fast_math mapping of tanhf:
// __expf has ~2^-21 max rel error; tanh.approx (what fast-math tanhf becomes) has 2^-10.66
// which compounds over 1024 recurrent steps. This stays ~1e-6.
__device__ __forceinline__ float my_tanh(float x) {
    float ax = fabsf(x);
    float e  = __expf(-2.0f * ax);          // (0,1], no overflow
    float r  = (1.0f - e) / (1.0f + e);     // tanh(|x|)
    return copysignf(r, x);
}

// ---------------------------------------------------------------------------
// Input projection: out[row][i] = sum_j in_row[j] * W[i][j] + b1[i] + b2[i]
// row = t*B + b. If SWAPPED, input row lives at (b*S + t)*K (layer-0 x is [B][S][D]);
// otherwise at row*K (seq buffers are [t][b][h]).
// Block: 256 threads, 64 output rows, processed in 8-row staged chunks.
// Thread (g = tid&31, rr = tid>>5): computes out[rr-th row of chunk][4g..4g+3].
// Inner loop: 1 LDS.128 (W^T) + 1 LDS.32 broadcast (x) per 4 FFMA -> FFMA-pipe bound.
// ---------------------------------------------------------------------------
template <int K, bool SWAPPED>
__global__ void proj_kernel(const float* __restrict__ in, const float* __restrict__ W,
                            const float* __restrict__ b1, const float* __restrict__ b2,
                            float* __restrict__ out) {
    extern __shared__ float sm[];
    float* Wt = sm;                // [K][PITCH] -> Wt[j*PITCH + i] = W[i*K + j]
    float* xs = sm + K * PITCH;    // [8][K]
    __shared__ float bs[HH];

    const int tid = threadIdx.x;

    // Load W transposed into smem (coalesced global read; one-time STS conflicts are fine).
    for (int idx = tid; idx < HH * K; idx += 256) {
        int i = idx / K;
        int j = idx - i * K;
        Wt[j * PITCH + i] = W[idx];
    }
    if (tid < HH) bs[tid] = b1[tid] + b2[tid];
    __syncthreads();

    const int g  = tid & 31;
    const int rr = tid >> 5;
    const int row0 = blockIdx.x * 64;

    for (int c = 0; c < 8; c++) {
        // Stage 8 input rows into smem.
        for (int idx = tid; idx < 8 * K; idx += 256) {
            int r = idx / K;
            int j = idx - r * K;
            int row = row0 + c * 8 + r;
            int t = row >> 9;          // B = 512
            int b = row & 511;
            int src = SWAPPED ? (b * SS + t) * K + j : row * K + j;
            xs[r * K + j] = in[src];
        }
        __syncthreads();

        float4 acc = *reinterpret_cast<const float4*>(&bs[4 * g]);
        const float* xrow = &xs[rr * K];
#pragma unroll
        for (int j = 0; j < K; j++) {
            float hj = xrow[j];
            float4 w = *reinterpret_cast<const float4*>(&Wt[j * PITCH + 4 * g]);
            acc.x = fmaf(hj, w.x, acc.x);
            acc.y = fmaf(hj, w.y, acc.y);
            acc.z = fmaf(hj, w.z, acc.z);
            acc.w = fmaf(hj, w.w, acc.w);
        }
        int row = row0 + c * 8 + rr;
        *reinterpret_cast<float4*>(&out[row * HH + 4 * g]) = acc;
        __syncthreads();
    }
}

// ---------------------------------------------------------------------------
// Recurrence: h_t = tanh(xw[t][b][:] + h_{t-1} @ W_hh^T), writes seq[t][b][:] = h_t.
// Grid 128 x 128 threads. Warp bl owns batch row b = blockIdx.x*4 + bl:
//   * W_hh^T in smem, shared by the 4 warps (one __syncthreads after load, then none).
//   * h double-buffered in per-warp smem rows -> only __syncwarp per step.
//   * xw_{t+1} prefetched from global during step t's compute.
// Per step per warp: 512 FFMA (4 accumulators) -> bound by FFMA issue (rt_SMSP=2).
// ---------------------------------------------------------------------------
__global__ void recur_kernel(const float* __restrict__ xw, const float* __restrict__ Whh,
                             float* __restrict__ seq) {
    extern __shared__ float sm[];
    float* Wt = sm;                  // [H][PITCH]
    float* h2 = sm + HH * PITCH;     // [2][4][H]

    const int tid = threadIdx.x;
    for (int idx = tid; idx < HH * HH; idx += 128) {
        int i = idx >> 7;
        int j = idx & 127;
        Wt[j * PITCH + i] = Whh[idx];
    }
    const int g  = tid & 31;
    const int bl = tid >> 5;
    const int b  = blockIdx.x * 4 + bl;

    // h0 = 0 (buffer 0)
    *reinterpret_cast<float4*>(&h2[bl * HH + 4 * g]) = make_float4(0.f, 0.f, 0.f, 0.f);
    __syncthreads();

    const float4* xwp = reinterpret_cast<const float4*>(xw + b * HH) + g;
    float4*       sqp = reinterpret_cast<float4*>(seq + b * HH) + g;
    const int stride4 = BB * HH / 4;   // float4 stride between timesteps

    float4 xnext = __ldg(xwp);
    int cur = 0;

    for (int t = 0; t < SS; t++) {
        float4 xv = xnext;
        if (t + 1 < SS) xnext = __ldg(xwp + (t + 1) * stride4);

        float a0 = xv.x, a1 = xv.y, a2 = xv.z, a3 = xv.w;
        const float* hr = &h2[cur * 4 * HH + bl * HH];
#pragma unroll
        for (int j = 0; j < HH; j++) {
            float hj = hr[j];
            float4 w = *reinterpret_cast<const float4*>(&Wt[j * PITCH + 4 * g]);
            a0 = fmaf(hj, w.x, a0);
            a1 = fmaf(hj, w.y, a1);
            a2 = fmaf(hj, w.z, a2);
            a3 = fmaf(hj, w.w, a3);
        }
        float4 hv = make_float4(my_tanh(a0), my_tanh(a1), my_tanh(a2), my_tanh(a3));

        int nxt = cur ^ 1;
        *reinterpret_cast<float4*>(&h2[nxt * 4 * HH + bl * HH + 4 * g]) = hv;
        sqp[t * stride4] = hv;
        __syncwarp();
        cur = nxt;
    }
}

// ---------------------------------------------------------------------------
// FC: out[b][c] = last[b][:] . fc_w[c][:] + fc_b[c]
// ---------------------------------------------------------------------------
__global__ void fc_kernel(const float* __restrict__ last, const float* __restrict__ fw,
                          const float* __restrict__ fb, float* __restrict__ out) {
    int idx = blockIdx.x * blockDim.x + threadIdx.x;
    if (idx >= BB * NC) return;
    int b = idx / NC;
    int c = idx - b * NC;
    const float4* xr = reinterpret_cast<const float4*>(last + b * HH);
    const float4* wr = reinterpret_cast<const float4*>(fw + c * HH);
    float acc = fb[c];
#pragma unroll
    for (int j = 0; j < HH / 4; j++) {
        float4 x = __ldg(xr + j);
        float4 w = __ldg(wr + j);
        acc = fmaf(x.x, w.x, fmaf(x.y, w.y, fmaf(x.z, w.z, fmaf(x.w, w.w, acc))));
    }
    out[idx] = acc;
}

extern "C" void kernel_launch(void* const* d_in, const int* in_sizes, int n_in,
                              void* d_out, int out_size) {
    const float* x     = (const float*)d_in[0];
    const float* w_ih0 = (const float*)d_in[1];
    const float* w_hh0 = (const float*)d_in[2];
    const float* b_ih0 = (const float*)d_in[3];
    const float* b_hh0 = (const float*)d_in[4];
    const float* w_ih  = (const float*)d_in[5];   // [3][H][H]
    const float* w_hh  = (const float*)d_in[6];   // [3][H][H]
    const float* b_ih  = (const float*)d_in[7];   // [3][H]
    const float* b_hh  = (const float*)d_in[8];   // [3][H]
    const float* fc_w  = (const float*)d_in[9];
    const float* fc_b  = (const float*)d_in[10];
    float* out = (float*)d_out;

    float *bufA, *bufB, *bufC;
    cudaGetSymbolAddress((void**)&bufA, g_bufA);
    cudaGetSymbolAddress((void**)&bufB, g_bufB);
    cudaGetSymbolAddress((void**)&bufC, g_bufC);

    const size_t smP128 = (size_t)(128 * PITCH + 8 * 128) * 4;   // ~72.7 KB
    const size_t smP28  = (size_t)(28 * PITCH + 8 * 28) * 4;     // ~15.7 KB
    const size_t smR    = (size_t)(HH * PITCH + 2 * 4 * HH) * 4; // ~71.7 KB

    cudaFuncSetAttribute(proj_kernel<128, false>, cudaFuncAttributeMaxDynamicSharedMemorySize, (int)smP128);
    cudaFuncSetAttribute(recur_kernel,            cudaFuncAttributeMaxDynamicSharedMemorySize, (int)smR);

    const int PROJ_BLOCKS = (SS * BB) / 64;   // 2048

    // Layer 0: x -> xw (bufB) -> seq (bufA)
    proj_kernel<DIN, true><<<PROJ_BLOCKS, 256, smP28>>>(x, w_ih0, b_ih0, b_hh0, bufB);
    recur_kernel<<<128, 128, smR>>>(bufB, w_hh0, bufA);

    // Layers 1..3: ping-pong A <-> C, xw always in bufB.
    // l=0: A -> B -> C ; l=1: C -> B -> A ; l=2: A -> B -> C
    float* seqs[2] = {bufA, bufC};
    for (int l = 0; l < 3; l++) {
        float* prev = seqs[l & 1];
        float* next = seqs[(l & 1) ^ 1];
        proj_kernel<HH, false><<<PROJ_BLOCKS, 256, smP128>>>(
            prev, w_ih + l * HH * HH, b_ih + l * HH, b_hh + l * HH, bufB);
        recur_kernel<<<128, 128, smR>>>(bufB, w_hh + l * HH * HH, next);
    }

    // Final FC on last timestep of layer-3 output (bufC).
    const float* last = bufC + (size_t)(SS - 1) * BB * HH;
    fc_kernel<<<(BB * NC + 127) / 128, 128>>>(last, fc_w, fc_b, out);
}

// round 6
// speedup vs baseline: 1.8034x; 1.1182x over previous
#include <cuda_runtime.h>
#include <math.h>

// RNN_472446402977: 4-layer tanh RNN + FC, fp32. B=512 S=256 D_IN=28 H=128 NC=10.
// R6: f32x2 packed FMA; recurrence reads W_hh once per SM per step (8-lane-shared
// reads, duplicated-h splat pairs); projections as register-tiled 128x128 GEMM.

#define BB 512
#define SS 256
#define DIN 28
#define HH 128
#define NC 10

typedef unsigned long long u64;

// Scratch (allocation-free): each [S][B][H] fp32 = 64MB.
__device__ float g_bufA[SS * BB * HH];
__device__ float g_bufB[SS * BB * HH];
__device__ float g_bufC[SS * BB * HH];

// ---- packed f32x2 helpers -------------------------------------------------
#define FMA2(acc, a, b) asm("fma.rn.f32x2 %0, %1, %2, %0;" : "+l"(acc) : "l"(a), "l"(b))

__device__ __forceinline__ u64 pk(float lo, float hi) {
    u64 r; asm("mov.b64 %0, {%1, %2};" : "=l"(r) : "f"(lo), "f"(hi)); return r;
}
__device__ __forceinline__ void upk(u64 v, float& lo, float& hi) {
    asm("mov.b64 {%0, %1}, %2;" : "=f"(lo), "=f"(hi) : "l"(v));
}

// Accurate tanh regardless of fast-math mapping of tanhf (~1e-6 rel).
__device__ __forceinline__ float my_tanh(float x) {
    float ax = fabsf(x);
    float e  = __expf(-2.0f * ax);
    float r  = (1.0f - e) / (1.0f + e);
    return copysignf(r, x);
}

// ---------------------------------------------------------------------------
// Projection GEMM: out[row][n] = sum_k A[row][k]*W[n][k] + (b1[n]+b2[n])
// M = S*B rows, N = 128, K in {128, 28}. 128x128 tile per CTA, 256 threads,
// 8 rows x 8 cols per thread, f32x2 accumulators paired over adjacent rows.
// Thread (mg = tid&15, ng = tid>>4): rows {4mg..4mg+3, 64+4mg..64+4mg+3},
// cols {8ng..8ng+7}. A staged transposed (As[k][m]) so row-pairs load as u64.
// ---------------------------------------------------------------------------
template <int K, int KC, bool SWAPPED>
__global__ __launch_bounds__(256, 2)
void proj_kernel(const float* __restrict__ A, const float* __restrict__ W,
                 const float* __restrict__ b1, const float* __restrict__ b2,
                 float* __restrict__ out) {
    extern __shared__ float sm[];
    float* Ws = sm;               // [K][132]   Ws[k][n] = W[n][k]
    float* As = sm + K * 132;     // [KC][132]  As[k][m]
    __shared__ float bs[HH];

    const int tid = threadIdx.x;

    for (int idx = tid; idx < HH * K; idx += 256) {
        int n = idx / K, k = idx - n * K;
        Ws[k * 132 + n] = W[idx];
    }
    if (tid < HH) bs[tid] = b1[tid] + b2[tid];

    const int mg = tid & 15, ng = tid >> 4;
    const int c0 = ng * 8;
    const int row0 = blockIdx.x * 128;

    __syncthreads();

    u64 acc[4][8];
#pragma unroll
    for (int c = 0; c < 8; c++) {
        float bv = bs[c0 + c];
        u64 p = pk(bv, bv);
        acc[0][c] = p; acc[1][c] = p; acc[2][c] = p; acc[3][c] = p;
    }

    for (int kc = 0; kc < K; kc += KC) {
        __syncthreads();
        // Stage As[kk][m] = A[row0+m][kc+4kq .. +4] (transposed, float4 reads)
        for (int idx = tid; idx < 128 * (KC / 4); idx += 256) {
            int m  = idx / (KC / 4);
            int kq = idx - m * (KC / 4);
            int row = row0 + m;
            const float* src;
            if (SWAPPED) {
                int t = row >> 9, b = row & 511;   // rows are t*B+b, x is [B][S][D]
                src = A + (b * SS + t) * K + kc + 4 * kq;
            } else {
                src = A + (size_t)row * K + kc + 4 * kq;
            }
            float4 v = *(const float4*)src;
            As[(4 * kq + 0) * 132 + m] = v.x;
            As[(4 * kq + 1) * 132 + m] = v.y;
            As[(4 * kq + 2) * 132 + m] = v.z;
            As[(4 * kq + 3) * 132 + m] = v.w;
        }
        __syncthreads();

#pragma unroll 4
        for (int k = 0; k < KC; k++) {
            const float* asr = &As[k * 132 + 4 * mg];
            ulonglong2 aA = *(const ulonglong2*)asr;          // rows 4mg..4mg+3
            ulonglong2 aB = *(const ulonglong2*)(asr + 64);   // rows 64+4mg..+3
            const float* wsr = &Ws[(kc + k) * 132 + c0];
            float4 wf0 = *(const float4*)wsr;
            float4 wf1 = *(const float4*)(wsr + 4);
            u64 ws[8];
            ws[0] = pk(wf0.x, wf0.x); ws[1] = pk(wf0.y, wf0.y);
            ws[2] = pk(wf0.z, wf0.z); ws[3] = pk(wf0.w, wf0.w);
            ws[4] = pk(wf1.x, wf1.x); ws[5] = pk(wf1.y, wf1.y);
            ws[6] = pk(wf1.z, wf1.z); ws[7] = pk(wf1.w, wf1.w);
#pragma unroll
            for (int c = 0; c < 8; c++) {
                FMA2(acc[0][c], aA.x, ws[c]);
                FMA2(acc[1][c], aA.y, ws[c]);
                FMA2(acc[2][c], aB.x, ws[c]);
                FMA2(acc[3][c], aB.y, ws[c]);
            }
        }
    }

#pragma unroll
    for (int rp = 0; rp < 4; rp++) {
        int mloc = (rp < 2) ? (4 * mg + 2 * rp) : (64 + 4 * mg + 2 * (rp - 2));
        float lo[8], hi[8];
#pragma unroll
        for (int c = 0; c < 8; c++) upk(acc[rp][c], lo[c], hi[c]);
        size_t row = row0 + mloc;
        *(float4*)&out[row * HH + c0]           = make_float4(lo[0], lo[1], lo[2], lo[3]);
        *(float4*)&out[row * HH + c0 + 4]       = make_float4(lo[4], lo[5], lo[6], lo[7]);
        *(float4*)&out[(row + 1) * HH + c0]     = make_float4(hi[0], hi[1], hi[2], hi[3]);
        *(float4*)&out[(row + 1) * HH + c0 + 4] = make_float4(hi[4], hi[5], hi[6], hi[7]);
    }
}

// ---------------------------------------------------------------------------
// Recurrence: h_t = tanh(xw_t + h_{t-1} @ Whh^T). 128 CTAs x 128 thr, 4 rows/CTA.
// Warp w computes outputs i in [32w,32w+32) for ALL 4 rows; lane g: row r=g>>3,
// i0 = 32w+4(g&7). Per j the warp reads ONE 128B W slice (8-lane broadcast ->
// W read exactly once per SM per step = crossbar minimum) and one 16B dup-h
// quad = two (h,h) f32x2 splats. 2 FMA2 per j per lane. __syncthreads per step,
// h double-buffered in duplicated layout hd[buf][r][2i..2i+1]=h[r][i].
// ---------------------------------------------------------------------------
__global__ __launch_bounds__(128, 1)
void recur_kernel(const float* __restrict__ xw, const float* __restrict__ Whh,
                  float* __restrict__ seq) {
    extern __shared__ float sm[];
    float* Wt = sm;                  // [128][132], Wt[j][i] = Whh[i][j]
    float* hd = sm + HH * 132;       // [2][4][264] duplicated h

    const int tid = threadIdx.x;
#pragma unroll 4
    for (int i = 0; i < HH; i++)
        Wt[tid * 132 + i] = Whh[i * HH + tid];

    const int g  = tid & 31;
    const int w  = tid >> 5;
    const int r  = g >> 3;
    const int i0 = 32 * w + 4 * (g & 7);
    const int b  = blockIdx.x * 4 + r;

    // h0 = 0 in buffer 0 (each lane zeroes its 8 duplicated floats)
    *(float4*)&hd[r * 264 + 2 * i0]     = make_float4(0.f, 0.f, 0.f, 0.f);
    *(float4*)&hd[r * 264 + 2 * i0 + 4] = make_float4(0.f, 0.f, 0.f, 0.f);
    __syncthreads();

    const float* xp = xw  + b * HH + i0;
    float*       sp = seq + b * HH + i0;
    const float* wr = Wt + i0;

    float4 xv  = *(const float4*)xp;              // t = 0
    float4 xn  = *(const float4*)(xp + BB * HH);  // t = 1
    int cur = 0;

    for (int t = 0; t < SS; t++) {
        u64 acc0 = pk(xv.x, xv.y);   // outputs i0, i0+1
        u64 acc1 = pk(xv.z, xv.w);   // outputs i0+2, i0+3
        const float* hr = hd + cur * 1056 + r * 264;

#pragma unroll 16
        for (int j = 0; j < HH; j += 2) {
            ulonglong2 hq = *(const ulonglong2*)(hr + 2 * j);        // (hj,hj),(hj+1,hj+1)
            ulonglong2 w0 = *(const ulonglong2*)(wr + j * 132);
            ulonglong2 w1 = *(const ulonglong2*)(wr + (j + 1) * 132);
            FMA2(acc0, hq.x, w0.x);
            FMA2(acc1, hq.x, w0.y);
            FMA2(acc0, hq.y, w1.x);
            FMA2(acc1, hq.y, w1.y);
        }

        float4 xn2 = xn;
        if (t + 2 < SS) xn2 = *(const float4*)(xp + (t + 2) * BB * HH);

        float a0, a1, a2, a3;
        upk(acc0, a0, a1); upk(acc1, a2, a3);
        float t0 = my_tanh(a0), t1 = my_tanh(a1), t2 = my_tanh(a2), t3 = my_tanh(a3);

        int nxt = cur ^ 1;
        float* hw = hd + nxt * 1056 + r * 264 + 2 * i0;
        *(float4*)hw       = make_float4(t0, t0, t1, t1);
        *(float4*)(hw + 4) = make_float4(t2, t2, t3, t3);
        *(float4*)(sp + (size_t)t * BB * HH) = make_float4(t0, t1, t2, t3);

        __syncthreads();
        cur = nxt;
        xv = xn; xn = xn2;
    }
}

// ---------------------------------------------------------------------------
// FC: out[b][c] = last[b][:] . fc_w[c][:] + fc_b[c]
// ---------------------------------------------------------------------------
__global__ void fc_kernel(const float* __restrict__ last, const float* __restrict__ fw,
                          const float* __restrict__ fb, float* __restrict__ out) {
    int idx = blockIdx.x * blockDim.x + threadIdx.x;
    if (idx >= BB * NC) return;
    int b = idx / NC;
    int c = idx - b * NC;
    const float4* xr = reinterpret_cast<const float4*>(last + b * HH);
    const float4* wr = reinterpret_cast<const float4*>(fw + c * HH);
    float acc = fb[c];
#pragma unroll
    for (int j = 0; j < HH / 4; j++) {
        float4 x = __ldg(xr + j);
        float4 w = __ldg(wr + j);
        acc = fmaf(x.x, w.x, fmaf(x.y, w.y, fmaf(x.z, w.z, fmaf(x.w, w.w, acc))));
    }
    out[idx] = acc;
}

extern "C" void kernel_launch(void* const* d_in, const int* in_sizes, int n_in,
                              void* d_out, int out_size) {
    const float* x     = (const float*)d_in[0];
    const float* w_ih0 = (const float*)d_in[1];
    const float* w_hh0 = (const float*)d_in[2];
    const float* b_ih0 = (const float*)d_in[3];
    const float* b_hh0 = (const float*)d_in[4];
    const float* w_ih  = (const float*)d_in[5];   // [3][H][H]
    const float* w_hh  = (const float*)d_in[6];   // [3][H][H]
    const float* b_ih  = (const float*)d_in[7];   // [3][H]
    const float* b_hh  = (const float*)d_in[8];   // [3][H]
    const float* fc_w  = (const float*)d_in[9];
    const float* fc_b  = (const float*)d_in[10];
    float* out = (float*)d_out;

    float *bufA, *bufB, *bufC;
    cudaGetSymbolAddress((void**)&bufA, g_bufA);
    cudaGetSymbolAddress((void**)&bufB, g_bufB);
    cudaGetSymbolAddress((void**)&bufC, g_bufC);

    const size_t smP128 = (size_t)(128 * 132 + 32 * 132) * 4;     // 84.5 KB
    const size_t smP28  = (size_t)(28 * 132 + 28 * 132) * 4;      // 29.6 KB
    const size_t smR    = (size_t)(HH * 132 + 2 * 4 * 264) * 4;   // 76.0 KB

    cudaFuncSetAttribute(proj_kernel<HH, 32, false>, cudaFuncAttributeMaxDynamicSharedMemorySize, (int)smP128);
    cudaFuncSetAttribute(proj_kernel<DIN, DIN, true>, cudaFuncAttributeMaxDynamicSharedMemorySize, (int)smP28);
    cudaFuncSetAttribute(recur_kernel, cudaFuncAttributeMaxDynamicSharedMemorySize, (int)smR);

    const int PROJ_BLOCKS = (SS * BB) / 128;   // 1024

    // Layer 0: x -> xw (bufB) -> seq (bufA)
    proj_kernel<DIN, DIN, true><<<PROJ_BLOCKS, 256, smP28>>>(x, w_ih0, b_ih0, b_hh0, bufB);
    recur_kernel<<<128, 128, smR>>>(bufB, w_hh0, bufA);

    // Layers 1..3: ping-pong A <-> C, xw always in bufB.
    float* seqs[2] = {bufA, bufC};
    for (int l = 0; l < 3; l++) {
        float* prev = seqs[l & 1];
        float* next = seqs[(l & 1) ^ 1];
        proj_kernel<HH, 32, false><<<PROJ_BLOCKS, 256, smP128>>>(
            prev, w_ih + l * HH * HH, b_ih + l * HH, b_hh + l * HH, bufB);
        recur_kernel<<<128, 128, smR>>>(bufB, w_hh + l * HH * HH, next);
    }

    // Final FC on last timestep of layer-3 output (bufC).
    const float* last = bufC + (size_t)(SS - 1) * BB * HH;
    fc_kernel<<<(BB * NC + 127) / 128, 128>>>(last, fc_w, fc_b, out);
}